// round 15
// baseline (speedup 1.0000x reference)
#include <cuda_runtime.h>
#include <cuda_bf16.h>
#include <math.h>

#define BATCH 8
#define NPTS  2048
#define KN    16
#define TPB   128
#define TILE  128
#define CAP   96
#define NTH   3
#define GDIM  6
#define NCELL (GDIM * GDIM * GDIM)
#define SEG   4
#define SEGLEN (NPTS / SEG)
#define BN    (BATCH * NPTS)
#define NPTS2 (2 * BN)
#define RED_BLKS 64
#define RED_TPB  256

// ---------------- scratch (no allocations allowed) ----------------
__device__ float g_rep[BN];
__device__ float g_nrm0[BN * 3];
__device__ float g_nrm1[BN * 3];
__device__ float4 g_sp[NPTS2];                  // sorted points (x,y,z,|p|^2)
__device__ unsigned short g_sj[NPTS2];          // sorted -> orig j
__device__ int   g_cs[2 * BATCH * (NCELL + 1)]; // cell start offsets
__device__ int   g_kc[NPTS2];                   // ksel | (cnt<<4); 15 = fallback
__device__ float g_cdp[NPTS2 * SEG];            // chamfer partial mins [pidx][seg]
__device__ float g_cd2buf[CAP * NPTS2];         // candidate d2 [slot][spidx]
__device__ unsigned short g_cidx[CAP * NPTS2];  // candidate orig idx [slot][spidx]
__device__ double g_part[RED_BLKS][4];

// pinned arithmetic shared by count & collect (must match exactly)
__device__ __forceinline__ float norm2f(float x, float y, float z) {
    return __fmaf_rn(x, x, __fmaf_rn(y, y, __fmul_rn(z, z)));
}
__device__ __forceinline__ float dist2f(float px, float py, float pz, float pn,
                                        float4 q) {
    float dot = __fmaf_rn(px, q.x, __fmaf_rn(py, q.y, __fmul_rn(pz, q.z)));
    return __fmaf_rn(-2.0f, dot, __fadd_rn(pn, q.w));
}
__device__ __forceinline__ float thv(int k) { return 0.024f * (float)(1 << k); }
__device__ __forceinline__ void cellrange(float p, float s, int& c0, int& c1) {
    c0 = max(0, (int)floorf((p - s) * (float)GDIM));
    c1 = min(GDIM - 1, (int)floorf((p + s) * (float)GDIM));
}

// =================== LAPACK single-precision ports =====================
// Faithful ports of the routines jax/XLA-CPU hits for jnp.linalg.eigh on a
// 3x3 f32 symmetric matrix (sign conventions must match the reference).

__device__ __forceinline__ float slapy2f(float x, float y) {
    float xa = fabsf(x), ya = fabsf(y);
    float w = fmaxf(xa, ya);
    float z = fminf(xa, ya);
    if (z == 0.0f) return w;
    float q = z / w;
    return w * sqrtf(1.0f + q * q);
}

__device__ __forceinline__ void slartgf(float f, float g, float& c, float& s, float& r) {
    const float safmin = 1.17549435e-38f;
    const float safmax = 1.0f / 1.17549435e-38f;
    const float rtmin  = 1.0842021725e-19f;
    const float rtmax  = 6.5219432e+18f;
    float f1 = fabsf(f), g1 = fabsf(g);
    if (g == 0.0f) {
        c = 1.0f; s = 0.0f; r = f;
    } else if (f == 0.0f) {
        c = 0.0f; s = copysignf(1.0f, g); r = g1;
    } else {
        float d;
        if (f1 > rtmin && f1 < rtmax && g1 > rtmin && g1 < rtmax) {
            d = sqrtf(f * f + g * g);
            c = f1 / d;
            r = copysignf(d, f);
        } else {
            float u  = fminf(safmax, fmaxf(safmin, fmaxf(f1, g1)));
            float fs = f / u, gs = g / u;
            d = sqrtf(fs * fs + gs * gs);
            c = fabsf(fs) / d;
            r = copysignf(d, f) * u;
        }
        s = g / r;
    }
}

__device__ void slaev2f(float a, float b, float cc,
                        float& rt1, float& rt2, float& cs1, float& sn1) {
    float sm  = a + cc;
    float df  = a - cc;
    float adf = fabsf(df);
    float tb  = b + b;
    float ab  = fabsf(tb);
    float acmx, acmn;
    if (fabsf(a) > fabsf(cc)) { acmx = a;  acmn = cc; }
    else                      { acmx = cc; acmn = a;  }
    float rt;
    if (adf > ab)      { float q = ab / adf; rt = adf * sqrtf(1.0f + q * q); }
    else if (adf < ab) { float q = adf / ab; rt = ab  * sqrtf(1.0f + q * q); }
    else               { rt = ab * sqrtf(2.0f); }
    int sgn1;
    if (sm < 0.0f) {
        rt1 = 0.5f * (sm - rt); sgn1 = -1;
        rt2 = (acmx / rt1) * acmn - (b / rt1) * b;
    } else if (sm > 0.0f) {
        rt1 = 0.5f * (sm + rt); sgn1 = 1;
        rt2 = (acmx / rt1) * acmn - (b / rt1) * b;
    } else {
        rt1 = 0.5f * rt; rt2 = -0.5f * rt; sgn1 = 1;
    }
    int sgn2;
    float cs;
    if (df >= 0.0f) { cs = df + rt; sgn2 = 1; }
    else            { cs = df - rt; sgn2 = -1; }
    float acs = fabsf(cs);
    if (acs > ab) {
        float ct = -tb / cs;
        sn1 = 1.0f / sqrtf(1.0f + ct * ct);
        cs1 = ct * sn1;
    } else {
        if (ab == 0.0f) { cs1 = 1.0f; sn1 = 0.0f; }
        else {
            float tn = -cs / tb;
            cs1 = 1.0f / sqrtf(1.0f + tn * tn);
            sn1 = tn * cs1;
        }
    }
    if (sgn1 == sgn2) { float tn = cs1; cs1 = -sn1; sn1 = tn; }
}

__device__ void ssteqr3(float d[4], float e[3], float z[4][4]) {
    const float eps    = 5.9604645e-08f;
    const float eps2   = eps * eps;
    const float safmin = 1.17549435e-38f;
    const float safmax = 1.0f / 1.17549435e-38f;
    const float ssfmax = sqrtf(safmax) / 3.0f;
    const float ssfmin = sqrtf(safmin) / eps2;
    const int n = 3;

    for (int i = 1; i <= 3; ++i)
        for (int j = 1; j <= 3; ++j)
            z[i][j] = (i == j) ? 1.0f : 0.0f;

    int nmaxit = n * 30, jtot = 0;
    int l1 = 1;
    int l = 1, m = 1, lsv = 1, lend = 1, lendsv = 1, iscale = 0;
    float anorm = 0.0f, p, g, r, c, s, f, b, rt1, rt2;
    float wc[3], ws[3];

L10:
    if (l1 > n) goto L160;
    if (l1 > 1) e[l1 - 1] = 0.0f;
    if (l1 <= n - 1) {
        for (m = l1; m <= n - 1; ++m) {
            float tst = fabsf(e[m]);
            if (tst == 0.0f) goto L30;
            if (tst <= (sqrtf(fabsf(d[m])) * sqrtf(fabsf(d[m + 1]))) * eps) {
                e[m] = 0.0f;
                goto L30;
            }
        }
    }
    m = n;
L30:
    l = l1; lsv = l; lend = m; lendsv = lend; l1 = m + 1;
    if (lend == l) goto L10;

    anorm = 0.0f;
    for (int i = l; i <= lend; ++i)     anorm = fmaxf(anorm, fabsf(d[i]));
    for (int i = l; i <= lend - 1; ++i) anorm = fmaxf(anorm, fabsf(e[i]));
    iscale = 0;
    if (anorm == 0.0f) goto L10;
    if (anorm > ssfmax) {
        iscale = 1;
        float mul = ssfmax / anorm;
        for (int i = l; i <= lend; ++i)     d[i] *= mul;
        for (int i = l; i <= lend - 1; ++i) e[i] *= mul;
    } else if (anorm < ssfmin) {
        iscale = 2;
        float mul = ssfmin / anorm;
        for (int i = l; i <= lend; ++i)     d[i] *= mul;
        for (int i = l; i <= lend - 1; ++i) e[i] *= mul;
    }

    if (fabsf(d[lend]) < fabsf(d[l])) { lend = lsv; l = lendsv; }

    if (lend > l) {
L40:
        if (l != lend) {
            for (m = l; m <= lend - 1; ++m) {
                float tst = fabsf(e[m]); tst = tst * tst;
                if (tst <= (eps2 * fabsf(d[m])) * fabsf(d[m + 1]) + safmin) goto L60;
            }
        }
        m = lend;
L60:
        if (m < lend) e[m] = 0.0f;
        p = d[l];
        if (m == l) goto L80;
        if (m == l + 1) {
            slaev2f(d[l], e[l], d[l + 1], rt1, rt2, c, s);
            {
                float ct = c, st = s;
                if (!(ct == 1.0f && st == 0.0f)) {
                    for (int i = 1; i <= 3; ++i) {
                        float temp   = z[i][l + 1];
                        z[i][l + 1]  = ct * temp - st * z[i][l];
                        z[i][l]      = st * temp + ct * z[i][l];
                    }
                }
            }
            d[l] = rt1; d[l + 1] = rt2; e[l] = 0.0f;
            l += 2;
            if (l <= lend) goto L40;
            goto L140;
        }
        if (jtot == nmaxit) goto L140;
        ++jtot;
        g = (d[l + 1] - p) / (2.0f * e[l]);
        r = slapy2f(g, 1.0f);
        g = d[m] - p + (e[l] / (g + copysignf(r, g)));
        s = 1.0f; c = 1.0f; p = 0.0f;
        for (int i = m - 1; i >= l; --i) {
            f = s * e[i]; b = c * e[i];
            slartgf(g, f, c, s, r);
            if (i != m - 1) e[i + 1] = r;
            g = d[i + 1] - p;
            r = (d[i] - g) * s + 2.0f * c * b;
            p = s * r;
            d[i + 1] = g + p;
            g = c * r - b;
            wc[i] = c; ws[i] = -s;
        }
        {
            int mm = m - l + 1;
            for (int j = mm - 1; j >= 1; --j) {
                float ct = wc[l + j - 1], st = ws[l + j - 1];
                if (!(ct == 1.0f && st == 0.0f)) {
                    for (int i = 1; i <= 3; ++i) {
                        float temp       = z[i][l + j];
                        z[i][l + j]      = ct * temp - st * z[i][l + j - 1];
                        z[i][l + j - 1]  = st * temp + ct * z[i][l + j - 1];
                    }
                }
            }
        }
        d[l] -= p;
        e[l] = g;
        goto L40;
L80:
        d[l] = p;
        ++l;
        if (l <= lend) goto L40;
        goto L140;
    } else {
L90:
        if (l != lend) {
            for (m = l; m >= lend + 1; --m) {
                float tst = fabsf(e[m - 1]); tst = tst * tst;
                if (tst <= (eps2 * fabsf(d[m])) * fabsf(d[m - 1]) + safmin) goto L110;
            }
        }
        m = lend;
L110:
        if (m > lend) e[m - 1] = 0.0f;
        p = d[l];
        if (m == l) goto L130;
        if (m == l - 1) {
            slaev2f(d[l - 1], e[l - 1], d[l], rt1, rt2, c, s);
            {
                float ct = c, st = s;
                if (!(ct == 1.0f && st == 0.0f)) {
                    for (int i = 1; i <= 3; ++i) {
                        float temp  = z[i][l];
                        z[i][l]     = ct * temp - st * z[i][l - 1];
                        z[i][l - 1] = st * temp + ct * z[i][l - 1];
                    }
                }
            }
            d[l - 1] = rt1; d[l] = rt2; e[l - 1] = 0.0f;
            l -= 2;
            if (l >= lend) goto L90;
            goto L140;
        }
        if (jtot == nmaxit) goto L140;
        ++jtot;
        g = (d[l - 1] - p) / (2.0f * e[l - 1]);
        r = slapy2f(g, 1.0f);
        g = d[m] - p + (e[l - 1] / (g + copysignf(r, g)));
        s = 1.0f; c = 1.0f; p = 0.0f;
        for (int i = m; i <= l - 1; ++i) {
            f = s * e[i]; b = c * e[i];
            slartgf(g, f, c, s, r);
            if (i != m) e[i - 1] = r;
            g = d[i] - p;
            r = (d[i + 1] - g) * s + 2.0f * c * b;
            p = s * r;
            d[i] = g + p;
            g = c * r - b;
            wc[i] = c; ws[i] = s;
        }
        {
            int mm = l - m + 1;
            for (int j = 1; j <= mm - 1; ++j) {
                float ct = wc[m + j - 1], st = ws[m + j - 1];
                if (!(ct == 1.0f && st == 0.0f)) {
                    for (int i = 1; i <= 3; ++i) {
                        float temp       = z[i][m + j];
                        z[i][m + j]      = ct * temp - st * z[i][m + j - 1];
                        z[i][m + j - 1]  = st * temp + ct * z[i][m + j - 1];
                    }
                }
            }
        }
        d[l] -= p;
        e[l - 1] = g;
        goto L90;
L130:
        d[l] = p;
        --l;
        if (l >= lend) goto L90;
        goto L140;
    }

L140:
    if (iscale == 1) {
        float mul = anorm / ssfmax;
        for (int i = lsv; i <= lendsv; ++i)     d[i] *= mul;
        for (int i = lsv; i <= lendsv - 1; ++i) e[i] *= mul;
    } else if (iscale == 2) {
        float mul = anorm / ssfmin;
        for (int i = lsv; i <= lendsv; ++i)     d[i] *= mul;
        for (int i = lsv; i <= lendsv - 1; ++i) e[i] *= mul;
    }
    if (jtot < nmaxit) goto L10;
    goto L160;

L160:
    for (int ii = 2; ii <= n; ++ii) {
        int i = ii - 1, k = i;
        float pp = d[i];
        for (int j = ii; j <= n; ++j)
            if (d[j] < pp) { k = j; pp = d[j]; }
        if (k != i) {
            d[k] = d[i]; d[i] = pp;
            for (int rr = 1; rr <= 3; ++rr) {
                float t = z[rr][i]; z[rr][i] = z[rr][k]; z[rr][k] = t;
            }
        }
    }
}

__device__ void eigvec_smallest3(const float cov[6], float nrm[3]) {
    float a00 = cov[0], a10 = cov[1], a20 = cov[2];
    float a11 = cov[3], a21 = cov[4], a22 = cov[5];

    float tau1, beta, v2 = 0.0f;
    float xnorm = fabsf(a20);
    if (xnorm == 0.0f) {
        tau1 = 0.0f; beta = a10;
    } else {
        beta = -copysignf(slapy2f(a10, xnorm), a10);
        tau1 = (beta - a10) / beta;
        v2   = a20 / (a10 - beta);
    }
    float e0 = beta;
    if (tau1 != 0.0f) {
        float x0 = tau1 * (a11 + a21 * v2);
        float x1 = tau1 * (a21 + a22 * v2);
        float al = -0.5f * tau1 * (x0 + x1 * v2);
        x0 += al; x1 += al * v2;
        a11 = a11 - x0 - x0;
        a21 = a21 - v2 * x0 - x1;
        a22 = a22 - v2 * x1 - v2 * x1;
    }
    float d[4] = {0.0f, a00, a11, a22};
    float e[3] = {0.0f, e0, a21};
    float z[4][4];
    ssteqr3(d, e, z);

    float z1 = z[1][1], z2 = z[2][1], z3 = z[3][1];
    if (tau1 != 0.0f) {
        float w = z2 + v2 * z3;
        z2 -= tau1 * w;
        z3 -= tau1 * w * v2;
    }
    nrm[0] = z1; nrm[1] = z2; nrm[2] = z3;
}

// ===== K0: deterministic grid build (bitonic sort of cid*2048+j) =======
__global__ void __launch_bounds__(256) grid_build_kernel(
    const float* __restrict__ pred, const float* __restrict__ gt) {
    const int sb = blockIdx.x;                 // side*BATCH + b
    const int side = sb / BATCH, b = sb % BATCH;
    const float* P = (side ? gt : pred) + (size_t)b * NPTS * 3;
    const int tid = threadIdx.x;

    __shared__ unsigned int skey[NPTS];
    __shared__ int cstart[NCELL + 1];

    for (int j = tid; j < NPTS; j += 256) {
        float x = P[j * 3 + 0], y = P[j * 3 + 1], z = P[j * 3 + 2];
        int cx = min(GDIM - 1, max(0, (int)(x * (float)GDIM)));
        int cy = min(GDIM - 1, max(0, (int)(y * (float)GDIM)));
        int cz = min(GDIM - 1, max(0, (int)(z * (float)GDIM)));
        unsigned int cid = (unsigned)((cz * GDIM + cy) * GDIM + cx);
        skey[j] = (cid << 11) | (unsigned)j;   // 2048 = 2^11
    }

    // bitonic sort (ascending) — unique keys -> deterministic stable order
    for (int k = 2; k <= NPTS; k <<= 1) {
        for (int jj = k >> 1; jj > 0; jj >>= 1) {
            __syncthreads();
            for (int t = tid; t < NPTS / 2; t += 256) {
                int i1 = 2 * t - (t & (jj - 1));
                int i2 = i1 + jj;
                bool up = ((i1 & k) == 0);
                unsigned int a = skey[i1], bb = skey[i2];
                if ((a > bb) == up) { skey[i1] = bb; skey[i2] = a; }
            }
        }
    }
    __syncthreads();

    for (int c = tid; c <= NCELL; c += 256) cstart[c] = -1;
    __syncthreads();
    for (int r = tid; r < NPTS; r += 256) {
        int cid = (int)(skey[r] >> 11);
        int prev = (r == 0) ? -1 : (int)(skey[r - 1] >> 11);
        if (cid != prev) cstart[cid] = r;
    }
    __syncthreads();
    if (tid == 0) {
        cstart[NCELL] = NPTS;
        for (int c = NCELL - 1; c >= 0; --c)
            if (cstart[c] < 0) cstart[c] = cstart[c + 1];
    }
    __syncthreads();

    for (int c = tid; c <= NCELL; c += 256)
        g_cs[sb * (NCELL + 1) + c] = cstart[c];
    for (int r = tid; r < NPTS; r += 256) {
        int j = (int)(skey[r] & 2047u);
        float x = P[j * 3 + 0], y = P[j * 3 + 1], z = P[j * 3 + 2];
        g_sp[(size_t)sb * NPTS + r] = make_float4(x, y, z, norm2f(x, y, z));
        g_sj[(size_t)sb * NPTS + r] = (unsigned short)j;
    }
}

// ===== K1: windowed progressive count -> ksel, cnt =====================
__global__ void __launch_bounds__(TPB) count_kernel() {
    const int side = blockIdx.z, b = blockIdx.y;
    const int sb = side * BATCH + b;
    const int spbase = sb * NPTS;
    const int tid = threadIdx.x;

    __shared__ int cs[NCELL + 1];
    for (int t = tid; t <= NCELL; t += TPB) cs[t] = g_cs[sb * (NCELL + 1) + t];
    __syncthreads();

    const int rank = blockIdx.x * TPB + tid;
    const float4 me = g_sp[spbase + rank];

    bool need = true;
    int out = 15;
    for (int k = 0; k < NTH; ++k) {
        if (!__any_sync(0xffffffffu, need)) break;
        const float T = thv(k);
        const float s = sqrtf(T) * 1.001f;   // conservative: d2<T => |dx|<s
        if (need) {
            int cx0, cx1, cy0, cy1, cz0, cz1;
            cellrange(me.x, s, cx0, cx1);
            cellrange(me.y, s, cy0, cy1);
            cellrange(me.z, s, cz0, cz1);
            int c = 0;
            for (int cz = cz0; cz <= cz1; ++cz)
                for (int cy = cy0; cy <= cy1; ++cy) {
                    int row = (cz * GDIM + cy) * GDIM;
                    int rs = cs[row + cx0], re = cs[row + cx1 + 1];
                    for (int idx = rs; idx < re; ++idx) {
                        float4 q = g_sp[spbase + idx];
                        c += (dist2f(me.x, me.y, me.z, me.w, q) < T) ? 1 : 0;
                    }
                }
            if (c >= KN) {
                if (c <= CAP) out = k | (c << 4);   // else stays 15 (fallback)
                need = false;
            }
        }
    }
    g_kc[spbase + rank] = out;
}

// ===== K2: windowed collect (identical window + compare as count) ======
__global__ void __launch_bounds__(TPB) collect_kernel() {
    const int side = blockIdx.z, b = blockIdx.y;
    const int sb = side * BATCH + b;
    const int spbase = sb * NPTS;
    const int tid = threadIdx.x;

    __shared__ int cs[NCELL + 1];
    for (int t = tid; t <= NCELL; t += TPB) cs[t] = g_cs[sb * (NCELL + 1) + t];
    __syncthreads();

    const int rank = blockIdx.x * TPB + tid;
    const int spidx = spbase + rank;
    const int v = g_kc[spidx];
    const int ksel = v & 15;
    if (ksel == 15) return;                      // fallback handled in mega

    const float4 me = g_sp[spidx];
    const float T = thv(ksel);
    const float s = sqrtf(T) * 1.001f;

    int cx0, cx1, cy0, cy1, cz0, cz1;
    cellrange(me.x, s, cx0, cx1);
    cellrange(me.y, s, cy0, cy1);
    cellrange(me.z, s, cz0, cz1);
    int slot = 0;
    for (int cz = cz0; cz <= cz1; ++cz)
        for (int cy = cy0; cy <= cy1; ++cy) {
            int row = (cz * GDIM + cy) * GDIM;
            int rs = cs[row + cx0], re = cs[row + cx1 + 1];
            for (int idx = rs; idx < re; ++idx) {
                float4 q = g_sp[spbase + idx];
                float d2 = dist2f(me.x, me.y, me.z, me.w, q);
                if (d2 < T && slot < CAP) {
                    g_cd2buf[(size_t)slot * NPTS2 + spidx] = d2;
                    g_cidx[(size_t)slot * NPTS2 + spidx] = g_sj[spbase + idx];
                    ++slot;
                }
            }
        }
}

// === K3: heterogeneous mega: chamfer blocks + (extract+normals) blocks ==
__device__ __forceinline__ void insert16(float (&key)[KN], int (&kid)[KN],
                                          float cd, int ci) {
    bool carry = true;
#pragma unroll
    for (int k = KN - 1; k > 0; --k) {
        bool mv = carry && (cd < key[k - 1]);
        float nk = mv ? key[k - 1] : cd;
        int   ni = mv ? kid[k - 1] : ci;
        if (carry) { key[k] = nk; kid[k] = ni; }
        carry = mv;
    }
    if (carry) { key[0] = cd; kid[0] = ci; }
}

// dynamic smem: float4 tile[TILE] | float d2buf[CAP][TPB] | u16 idxbuf[CAP][TPB]
#define MEGA_SMEM (TILE * 16 + CAP * TPB * 4 + CAP * TPB * 2)

__global__ void __launch_bounds__(TPB) mega_kernel(
    const float* __restrict__ pred, const float* __restrict__ gt) {
    extern __shared__ char sm[];
    float4* s = (float4*)sm;
    const int b = blockIdx.y;
    const int tid = threadIdx.x;

    if (blockIdx.z >= 2) {
        // ------------- chamfer role (verbatim R11) ----------------------
        const int zz = blockIdx.z - 2;
        const int side = zz / SEG;
        const int seg  = zz % SEG;
        const int i = blockIdx.x * TPB + tid;
        const float* P = (side ? gt : pred) + (size_t)b * NPTS * 3;
        const float* Q = (side ? pred : gt) + (size_t)b * NPTS * 3;

        const float px = P[i * 3 + 0], py = P[i * 3 + 1], pz = P[i * 3 + 2];
        const float pn = norm2f(px, py, pz);
        const int j0 = seg * SEGLEN;

        float cm[4];
#pragma unroll
        for (int u = 0; u < 4; ++u) cm[u] = __int_as_float(0x7f800000);
        for (int tile = 0; tile < SEGLEN; tile += TILE) {
            __syncthreads();
            {
                int j = j0 + tile + tid;
                float qx = Q[j * 3 + 0], qy = Q[j * 3 + 1], qz = Q[j * 3 + 2];
                s[tid] = make_float4(qx, qy, qz, norm2f(qx, qy, qz));
            }
            __syncthreads();
#pragma unroll 4
            for (int t0 = 0; t0 < TILE; t0 += 4) {
#pragma unroll
                for (int u = 0; u < 4; ++u)
                    cm[u] = fminf(cm[u], dist2f(px, py, pz, pn, s[t0 + u]));
            }
        }
        float cmin = fminf(fminf(cm[0], cm[1]), fminf(cm[2], cm[3]));
        g_cdp[((size_t)(side * BATCH + b) * NPTS + i) * SEG + seg] = cmin;
        return;
    }

    // ------------- extract + normals role (sorted-rank indexed) ---------
    float* d2buf = (float*)(sm + TILE * 16);
    unsigned short* idxbuf = (unsigned short*)(sm + TILE * 16 + CAP * TPB * 4);

    const int side = blockIdx.z;
    const int rank = blockIdx.x * TPB + tid;
    const int spidx = (side * BATCH + b) * NPTS + rank;
    const float* P = (side ? gt : pred) + (size_t)b * NPTS * 3;

    const float4 me = g_sp[spidx];
    const int oi = (int)g_sj[spidx];             // original point index
    const int v = g_kc[spidx];
    const int ksel = v & 15;
    const int cnt = (ksel == 15) ? -1 : (v >> 4);

    float key[KN]; int kid[KN];

    const int anyfb = __syncthreads_or((cnt < KN) ? 1 : 0);

    if (anyfb) {
        // block-uniform exact fallback: full insert scan (orig j order)
#pragma unroll
        for (int k = 0; k < KN; ++k) { key[k] = __int_as_float(0x7f800000); kid[k] = 0; }
        for (int tile = 0; tile < NPTS; tile += TILE) {
            __syncthreads();
            {
                int j = tile + tid;
                float qx = P[j * 3 + 0], qy = P[j * 3 + 1], qz = P[j * 3 + 2];
                s[tid] = make_float4(qx, qy, qz, norm2f(qx, qy, qz));
            }
            __syncthreads();
            for (int t = 0; t < TILE; ++t) {
                float d2 = dist2f(me.x, me.y, me.z, me.w, s[t]);
                if (d2 < key[KN - 1]) insert16(key, kid, d2, tile + t);
            }
        }
    } else {
        // stream candidates global->smem (coalesced across the warp)
        for (int slot = 0; slot < cnt; ++slot) {
            d2buf[slot * TPB + tid]  = g_cd2buf[(size_t)slot * NPTS2 + spidx];
            idxbuf[slot * TPB + tid] = g_cidx[(size_t)slot * NPTS2 + spidx];
        }
        // stable strict-min extraction over candidates (exact top-16 set)
#pragma unroll
        for (int r = 0; r < KN; ++r) {
            float best = __int_as_float(0x7f800000);
            int bslot = 0;
            for (int j = 0; j < cnt; ++j) {
                float vv = d2buf[j * TPB + tid];
                if (vv < best) { best = vv; bslot = j; }
            }
            key[r] = best;
            kid[r] = (int)idxbuf[bslot * TPB + tid];
            d2buf[bslot * TPB + tid] = __int_as_float(0x7f800000);
        }
    }

    // ---- repulsion from entries 1..4 (entry 0 = self) ----
    float rep = 0.0f;
#pragma unroll
    for (int k = 1; k <= 4; ++k) {
        float dd = sqrtf(fmaxf(key[k], 1e-12f));
        rep += fmaxf(0.02f - dd, 0.0f);
    }
    if (side == 0) g_rep[b * NPTS + oi] = rep;

    // ---- fused normals epilogue (verbatim R11 math) ----
    float nbx[KN], nby[KN], nbz[KN];
#pragma unroll
    for (int k = 0; k < KN; ++k) {
        int j = kid[k];
        nbx[k] = P[j * 3 + 0]; nby[k] = P[j * 3 + 1]; nbz[k] = P[j * 3 + 2];
    }
    float mx = 0.0f, my = 0.0f, mz = 0.0f;
#pragma unroll
    for (int k = 0; k < KN; ++k) { mx += nbx[k]; my += nby[k]; mz += nbz[k]; }
    mx *= (1.0f / KN); my *= (1.0f / KN); mz *= (1.0f / KN);
    float cxx = 0, cxy = 0, cxz = 0, cyy = 0, cyz = 0, czz = 0;
#pragma unroll
    for (int k = 0; k < KN; ++k) {
        float dx = nbx[k] - mx, dy = nby[k] - my, dz = nbz[k] - mz;
        cxx += dx * dx; cxy += dx * dy; cxz += dx * dz;
        cyy += dy * dy; cyz += dy * dz; czz += dz * dz;
    }
    const float invK = 1.0f / KN;
    float cov[6] = {cxx * invK, cxy * invK, cxz * invK,
                    cyy * invK, cyz * invK, czz * invK};
    float nrm[3];
    eigvec_smallest3(cov, nrm);

    float* dst = (side == 0 ? g_nrm0 : g_nrm1) + (size_t)(b * NPTS + oi) * 3;
    dst[0] = nrm[0]; dst[1] = nrm[1]; dst[2] = nrm[2];
}

// ---- deterministic two-stage reduction ----
__global__ void __launch_bounds__(RED_TPB) reduce_stage1_kernel() {
    __shared__ double sh0[RED_TPB], sh1[RED_TPB], sh2[RED_TPB], sh3[RED_TPB];
    const int tid = threadIdx.x;
    const int blk = blockIdx.x;
    const int per_blk = BN / RED_BLKS;
    const int base = blk * per_blk;
    double c0 = 0.0, c1 = 0.0, rp = 0.0, dt = 0.0;
    for (int off = tid; off < per_blk; off += RED_TPB) {
        int idx = base + off;
        const float* p0 = g_cdp + (size_t)idx * SEG;
        float a0 = fminf(fminf(p0[0], p0[1]), fminf(p0[2], p0[3]));
        const float* p1 = g_cdp + (size_t)(idx + BN) * SEG;
        float a1 = fminf(fminf(p1[0], p1[1]), fminf(p1[2], p1[3]));
        c0 += (double)a0;
        c1 += (double)a1;
        rp += (double)g_rep[idx];
        float dd = g_nrm0[idx * 3 + 0] * g_nrm1[idx * 3 + 0]
                 + g_nrm0[idx * 3 + 1] * g_nrm1[idx * 3 + 1]
                 + g_nrm0[idx * 3 + 2] * g_nrm1[idx * 3 + 2];
        dt += (double)dd;
    }
    sh0[tid] = c0; sh1[tid] = c1; sh2[tid] = rp; sh3[tid] = dt;
    __syncthreads();
    for (int off = RED_TPB / 2; off > 0; off >>= 1) {
        if (tid < off) {
            sh0[tid] += sh0[tid + off];
            sh1[tid] += sh1[tid + off];
            sh2[tid] += sh2[tid + off];
            sh3[tid] += sh3[tid + off];
        }
        __syncthreads();
    }
    if (tid == 0) {
        g_part[blk][0] = sh0[0];
        g_part[blk][1] = sh1[0];
        g_part[blk][2] = sh2[0];
        g_part[blk][3] = sh3[0];
    }
}

__global__ void __launch_bounds__(RED_BLKS) reduce_stage2_kernel(float* __restrict__ out) {
    __shared__ double sh0[RED_BLKS], sh1[RED_BLKS], sh2[RED_BLKS], sh3[RED_BLKS];
    const int tid = threadIdx.x;
    sh0[tid] = g_part[tid][0];
    sh1[tid] = g_part[tid][1];
    sh2[tid] = g_part[tid][2];
    sh3[tid] = g_part[tid][3];
    __syncthreads();
    for (int off = RED_BLKS / 2; off > 0; off >>= 1) {
        if (tid < off) {
            sh0[tid] += sh0[tid + off];
            sh1[tid] += sh1[tid + off];
            sh2[tid] += sh2[tid + off];
            sh3[tid] += sh3[tid + off];
        }
        __syncthreads();
    }
    if (tid == 0) {
        const double inv = 1.0 / (double)BN;
        double cd    = (sh0[0] + sh1[0]) * inv;
        double rep   = sh2[0] / ((double)BN * 4.0);
        double normc = 1.0 - sh3[0] * inv;
        out[0] = (float)(cd + 0.1 * rep + 0.01 * normc);
    }
}

extern "C" void kernel_launch(void* const* d_in, const int* in_sizes, int n_in,
                              void* d_out, int out_size) {
    const float* pred = (const float*)d_in[0];
    const float* gt   = (const float*)d_in[1];
    cudaFuncSetAttribute(mega_kernel,
                         cudaFuncAttributeMaxDynamicSharedMemorySize, MEGA_SMEM);
    dim3 grid_pt(NPTS / TPB, BATCH, 2);
    dim3 grid_mega(NPTS / TPB, BATCH, 2 + 2 * SEG);
    grid_build_kernel<<<2 * BATCH, 256>>>(pred, gt);
    count_kernel<<<grid_pt, TPB>>>();
    collect_kernel<<<grid_pt, TPB>>>();
    mega_kernel<<<grid_mega, TPB, MEGA_SMEM>>>(pred, gt);
    reduce_stage1_kernel<<<RED_BLKS, RED_TPB>>>();
    reduce_stage2_kernel<<<1, RED_BLKS>>>((float*)d_out);
}

// round 16
// speedup vs baseline: 1.4224x; 1.4224x over previous
#include <cuda_runtime.h>
#include <cuda_bf16.h>
#include <math.h>

#define BATCH 8
#define NPTS  2048
#define KN    16
#define TPB   128
#define TILE  128
#define CAP   96
#define NTH   3
#define SEG   4
#define SEGLEN (NPTS / SEG)
#define BN    (BATCH * NPTS)
#define NPTS2 (2 * BN)
#define RED_BLKS 64
#define RED_TPB  256

// ---------------- scratch (no allocations allowed) ----------------
__device__ float g_rep[BN];
__device__ float g_nrm0[BN * 3];
__device__ float g_nrm1[BN * 3];
__device__ uint2 g_cntp[NPTS2 * SEG];           // per-seg counts [pidx][seg]
__device__ float g_cdp[NPTS2 * SEG];            // chamfer partial mins [pidx][seg]
__device__ float g_cd2buf[CAP * NPTS2];         // candidate d2 [slot][pidx]
__device__ unsigned short g_cidx[CAP * NPTS2];  // candidate idx [slot][pidx]
__device__ double g_part[RED_BLKS][4];

// pinned arithmetic shared by count & collect (must match exactly)
__device__ __forceinline__ float norm2f(float x, float y, float z) {
    return __fmaf_rn(x, x, __fmaf_rn(y, y, __fmul_rn(z, z)));
}
// full-form distance (fallback path only; internally consistent)
__device__ __forceinline__ float dist2f(float px, float py, float pz, float pn,
                                        float4 q) {
    float dot = __fmaf_rn(px, q.x, __fmaf_rn(py, q.y, __fmul_rn(pz, q.z)));
    return __fmaf_rn(-2.0f, dot, __fadd_rn(pn, q.w));
}
// transformed distance: d2' = |q|^2 - 2 p.q  (d2 = d2' + pn); shared by
// count & collect so threshold decisions agree bit-exactly.
__device__ __forceinline__ float dist2t(float ax, float ay, float az, float4 q) {
    return __fmaf_rn(ax, q.x, __fmaf_rn(ay, q.y, __fmaf_rn(az, q.z, q.w)));
}
__device__ __forceinline__ float thval(int k) { return 0.024f * (float)(1 << k); }
__device__ __forceinline__ int cnt_at(uint2 v, int k) {
    return (k == 0) ? (int)(v.x & 0xffffu)
         : (k == 1) ? (int)(v.x >> 16)
                    : (int)(v.y & 0xffffu);
}

// =================== LAPACK single-precision ports =====================
// Faithful ports of the routines jax/XLA-CPU hits for jnp.linalg.eigh on a
// 3x3 f32 symmetric matrix (sign conventions must match the reference).

__device__ __forceinline__ float slapy2f(float x, float y) {
    float xa = fabsf(x), ya = fabsf(y);
    float w = fmaxf(xa, ya);
    float z = fminf(xa, ya);
    if (z == 0.0f) return w;
    float q = z / w;
    return w * sqrtf(1.0f + q * q);
}

__device__ __forceinline__ void slartgf(float f, float g, float& c, float& s, float& r) {
    const float safmin = 1.17549435e-38f;
    const float safmax = 1.0f / 1.17549435e-38f;
    const float rtmin  = 1.0842021725e-19f;
    const float rtmax  = 6.5219432e+18f;
    float f1 = fabsf(f), g1 = fabsf(g);
    if (g == 0.0f) {
        c = 1.0f; s = 0.0f; r = f;
    } else if (f == 0.0f) {
        c = 0.0f; s = copysignf(1.0f, g); r = g1;
    } else {
        float d;
        if (f1 > rtmin && f1 < rtmax && g1 > rtmin && g1 < rtmax) {
            d = sqrtf(f * f + g * g);
            c = f1 / d;
            r = copysignf(d, f);
        } else {
            float u  = fminf(safmax, fmaxf(safmin, fmaxf(f1, g1)));
            float fs = f / u, gs = g / u;
            d = sqrtf(fs * fs + gs * gs);
            c = fabsf(fs) / d;
            r = copysignf(d, f) * u;
        }
        s = g / r;
    }
}

__device__ void slaev2f(float a, float b, float cc,
                        float& rt1, float& rt2, float& cs1, float& sn1) {
    float sm  = a + cc;
    float df  = a - cc;
    float adf = fabsf(df);
    float tb  = b + b;
    float ab  = fabsf(tb);
    float acmx, acmn;
    if (fabsf(a) > fabsf(cc)) { acmx = a;  acmn = cc; }
    else                      { acmx = cc; acmn = a;  }
    float rt;
    if (adf > ab)      { float q = ab / adf; rt = adf * sqrtf(1.0f + q * q); }
    else if (adf < ab) { float q = adf / ab; rt = ab  * sqrtf(1.0f + q * q); }
    else               { rt = ab * sqrtf(2.0f); }
    int sgn1;
    if (sm < 0.0f) {
        rt1 = 0.5f * (sm - rt); sgn1 = -1;
        rt2 = (acmx / rt1) * acmn - (b / rt1) * b;
    } else if (sm > 0.0f) {
        rt1 = 0.5f * (sm + rt); sgn1 = 1;
        rt2 = (acmx / rt1) * acmn - (b / rt1) * b;
    } else {
        rt1 = 0.5f * rt; rt2 = -0.5f * rt; sgn1 = 1;
    }
    int sgn2;
    float cs;
    if (df >= 0.0f) { cs = df + rt; sgn2 = 1; }
    else            { cs = df - rt; sgn2 = -1; }
    float acs = fabsf(cs);
    if (acs > ab) {
        float ct = -tb / cs;
        sn1 = 1.0f / sqrtf(1.0f + ct * ct);
        cs1 = ct * sn1;
    } else {
        if (ab == 0.0f) { cs1 = 1.0f; sn1 = 0.0f; }
        else {
            float tn = -cs / tb;
            cs1 = 1.0f / sqrtf(1.0f + tn * tn);
            sn1 = tn * cs1;
        }
    }
    if (sgn1 == sgn2) { float tn = cs1; cs1 = -sn1; sn1 = tn; }
}

__device__ void ssteqr3(float d[4], float e[3], float z[4][4]) {
    const float eps    = 5.9604645e-08f;
    const float eps2   = eps * eps;
    const float safmin = 1.17549435e-38f;
    const float safmax = 1.0f / 1.17549435e-38f;
    const float ssfmax = sqrtf(safmax) / 3.0f;
    const float ssfmin = sqrtf(safmin) / eps2;
    const int n = 3;

    for (int i = 1; i <= 3; ++i)
        for (int j = 1; j <= 3; ++j)
            z[i][j] = (i == j) ? 1.0f : 0.0f;

    int nmaxit = n * 30, jtot = 0;
    int l1 = 1;
    int l = 1, m = 1, lsv = 1, lend = 1, lendsv = 1, iscale = 0;
    float anorm = 0.0f, p, g, r, c, s, f, b, rt1, rt2;
    float wc[3], ws[3];

L10:
    if (l1 > n) goto L160;
    if (l1 > 1) e[l1 - 1] = 0.0f;
    if (l1 <= n - 1) {
        for (m = l1; m <= n - 1; ++m) {
            float tst = fabsf(e[m]);
            if (tst == 0.0f) goto L30;
            if (tst <= (sqrtf(fabsf(d[m])) * sqrtf(fabsf(d[m + 1]))) * eps) {
                e[m] = 0.0f;
                goto L30;
            }
        }
    }
    m = n;
L30:
    l = l1; lsv = l; lend = m; lendsv = lend; l1 = m + 1;
    if (lend == l) goto L10;

    anorm = 0.0f;
    for (int i = l; i <= lend; ++i)     anorm = fmaxf(anorm, fabsf(d[i]));
    for (int i = l; i <= lend - 1; ++i) anorm = fmaxf(anorm, fabsf(e[i]));
    iscale = 0;
    if (anorm == 0.0f) goto L10;
    if (anorm > ssfmax) {
        iscale = 1;
        float mul = ssfmax / anorm;
        for (int i = l; i <= lend; ++i)     d[i] *= mul;
        for (int i = l; i <= lend - 1; ++i) e[i] *= mul;
    } else if (anorm < ssfmin) {
        iscale = 2;
        float mul = ssfmin / anorm;
        for (int i = l; i <= lend; ++i)     d[i] *= mul;
        for (int i = l; i <= lend - 1; ++i) e[i] *= mul;
    }

    if (fabsf(d[lend]) < fabsf(d[l])) { lend = lsv; l = lendsv; }

    if (lend > l) {
L40:
        if (l != lend) {
            for (m = l; m <= lend - 1; ++m) {
                float tst = fabsf(e[m]); tst = tst * tst;
                if (tst <= (eps2 * fabsf(d[m])) * fabsf(d[m + 1]) + safmin) goto L60;
            }
        }
        m = lend;
L60:
        if (m < lend) e[m] = 0.0f;
        p = d[l];
        if (m == l) goto L80;
        if (m == l + 1) {
            slaev2f(d[l], e[l], d[l + 1], rt1, rt2, c, s);
            {
                float ct = c, st = s;
                if (!(ct == 1.0f && st == 0.0f)) {
                    for (int i = 1; i <= 3; ++i) {
                        float temp   = z[i][l + 1];
                        z[i][l + 1]  = ct * temp - st * z[i][l];
                        z[i][l]      = st * temp + ct * z[i][l];
                    }
                }
            }
            d[l] = rt1; d[l + 1] = rt2; e[l] = 0.0f;
            l += 2;
            if (l <= lend) goto L40;
            goto L140;
        }
        if (jtot == nmaxit) goto L140;
        ++jtot;
        g = (d[l + 1] - p) / (2.0f * e[l]);
        r = slapy2f(g, 1.0f);
        g = d[m] - p + (e[l] / (g + copysignf(r, g)));
        s = 1.0f; c = 1.0f; p = 0.0f;
        for (int i = m - 1; i >= l; --i) {
            f = s * e[i]; b = c * e[i];
            slartgf(g, f, c, s, r);
            if (i != m - 1) e[i + 1] = r;
            g = d[i + 1] - p;
            r = (d[i] - g) * s + 2.0f * c * b;
            p = s * r;
            d[i + 1] = g + p;
            g = c * r - b;
            wc[i] = c; ws[i] = -s;
        }
        {
            int mm = m - l + 1;
            for (int j = mm - 1; j >= 1; --j) {
                float ct = wc[l + j - 1], st = ws[l + j - 1];
                if (!(ct == 1.0f && st == 0.0f)) {
                    for (int i = 1; i <= 3; ++i) {
                        float temp       = z[i][l + j];
                        z[i][l + j]      = ct * temp - st * z[i][l + j - 1];
                        z[i][l + j - 1]  = st * temp + ct * z[i][l + j - 1];
                    }
                }
            }
        }
        d[l] -= p;
        e[l] = g;
        goto L40;
L80:
        d[l] = p;
        ++l;
        if (l <= lend) goto L40;
        goto L140;
    } else {
L90:
        if (l != lend) {
            for (m = l; m >= lend + 1; --m) {
                float tst = fabsf(e[m - 1]); tst = tst * tst;
                if (tst <= (eps2 * fabsf(d[m])) * fabsf(d[m - 1]) + safmin) goto L110;
            }
        }
        m = lend;
L110:
        if (m > lend) e[m - 1] = 0.0f;
        p = d[l];
        if (m == l) goto L130;
        if (m == l - 1) {
            slaev2f(d[l - 1], e[l - 1], d[l], rt1, rt2, c, s);
            {
                float ct = c, st = s;
                if (!(ct == 1.0f && st == 0.0f)) {
                    for (int i = 1; i <= 3; ++i) {
                        float temp  = z[i][l];
                        z[i][l]     = ct * temp - st * z[i][l - 1];
                        z[i][l - 1] = st * temp + ct * z[i][l - 1];
                    }
                }
            }
            d[l - 1] = rt1; d[l] = rt2; e[l - 1] = 0.0f;
            l -= 2;
            if (l >= lend) goto L90;
            goto L140;
        }
        if (jtot == nmaxit) goto L140;
        ++jtot;
        g = (d[l - 1] - p) / (2.0f * e[l - 1]);
        r = slapy2f(g, 1.0f);
        g = d[m] - p + (e[l - 1] / (g + copysignf(r, g)));
        s = 1.0f; c = 1.0f; p = 0.0f;
        for (int i = m; i <= l - 1; ++i) {
            f = s * e[i]; b = c * e[i];
            slartgf(g, f, c, s, r);
            if (i != m) e[i - 1] = r;
            g = d[i] - p;
            r = (d[i + 1] - g) * s + 2.0f * c * b;
            p = s * r;
            d[i] = g + p;
            g = c * r - b;
            wc[i] = c; ws[i] = s;
        }
        {
            int mm = l - m + 1;
            for (int j = 1; j <= mm - 1; ++j) {
                float ct = wc[m + j - 1], st = ws[m + j - 1];
                if (!(ct == 1.0f && st == 0.0f)) {
                    for (int i = 1; i <= 3; ++i) {
                        float temp       = z[i][m + j];
                        z[i][m + j]      = ct * temp - st * z[i][m + j - 1];
                        z[i][m + j - 1]  = st * temp + ct * z[i][m + j - 1];
                    }
                }
            }
        }
        d[l] -= p;
        e[l - 1] = g;
        goto L90;
L130:
        d[l] = p;
        --l;
        if (l >= lend) goto L90;
        goto L140;
    }

L140:
    if (iscale == 1) {
        float mul = anorm / ssfmax;
        for (int i = lsv; i <= lendsv; ++i)     d[i] *= mul;
        for (int i = lsv; i <= lendsv - 1; ++i) e[i] *= mul;
    } else if (iscale == 2) {
        float mul = anorm / ssfmin;
        for (int i = lsv; i <= lendsv; ++i)     d[i] *= mul;
        for (int i = lsv; i <= lendsv - 1; ++i) e[i] *= mul;
    }
    if (jtot < nmaxit) goto L10;
    goto L160;

L160:
    for (int ii = 2; ii <= n; ++ii) {
        int i = ii - 1, k = i;
        float pp = d[i];
        for (int j = ii; j <= n; ++j)
            if (d[j] < pp) { k = j; pp = d[j]; }
        if (k != i) {
            d[k] = d[i]; d[i] = pp;
            for (int rr = 1; rr <= 3; ++rr) {
                float t = z[rr][i]; z[rr][i] = z[rr][k]; z[rr][k] = t;
            }
        }
    }
}

__device__ void eigvec_smallest3(const float cov[6], float nrm[3]) {
    float a00 = cov[0], a10 = cov[1], a20 = cov[2];
    float a11 = cov[3], a21 = cov[4], a22 = cov[5];

    float tau1, beta, v2 = 0.0f;
    float xnorm = fabsf(a20);
    if (xnorm == 0.0f) {
        tau1 = 0.0f; beta = a10;
    } else {
        beta = -copysignf(slapy2f(a10, xnorm), a10);
        tau1 = (beta - a10) / beta;
        v2   = a20 / (a10 - beta);
    }
    float e0 = beta;
    if (tau1 != 0.0f) {
        float x0 = tau1 * (a11 + a21 * v2);
        float x1 = tau1 * (a21 + a22 * v2);
        float al = -0.5f * tau1 * (x0 + x1 * v2);
        x0 += al; x1 += al * v2;
        a11 = a11 - x0 - x0;
        a21 = a21 - v2 * x0 - x1;
        a22 = a22 - v2 * x1 - v2 * x1;
    }
    float d[4] = {0.0f, a00, a11, a22};
    float e[3] = {0.0f, e0, a21};
    float z[4][4];
    ssteqr3(d, e, z);

    float z1 = z[1][1], z2 = z[2][1], z3 = z[3][1];
    if (tau1 != 0.0f) {
        float w = z2 + v2 * z3;
        z2 -= tau1 * w;
        z3 -= tau1 * w * v2;
    }
    nrm[0] = z1; nrm[1] = z2; nrm[2] = z3;
}

// ==== K1: exact counts at NTH thresholds (transformed compare) =========
__global__ void __launch_bounds__(TPB) count_kernel(
    const float* __restrict__ pred, const float* __restrict__ gt) {
    const int side = blockIdx.z / SEG;
    const int seg  = blockIdx.z % SEG;
    const int b = blockIdx.y;
    const int i = blockIdx.x * TPB + threadIdx.x;
    const float* P = (side ? gt : pred) + (size_t)b * NPTS * 3;

    const float px = P[i * 3 + 0], py = P[i * 3 + 1], pz = P[i * 3 + 2];
    const float pn = norm2f(px, py, pz);
    const float ax = -2.0f * px, ay = -2.0f * py, az = -2.0f * pz;
    float tkp[NTH];
#pragma unroll
    for (int k = 0; k < NTH; ++k) tkp[k] = __fadd_rn(thval(k), -pn);

    __shared__ float4 s[TILE];
    const int j0 = seg * SEGLEN;
    int c[NTH];
#pragma unroll
    for (int k = 0; k < NTH; ++k) c[k] = 0;
    for (int tile = 0; tile < SEGLEN; tile += TILE) {
        __syncthreads();
        {
            int j = j0 + tile + threadIdx.x;
            float qx = P[j * 3 + 0], qy = P[j * 3 + 1], qz = P[j * 3 + 2];
            s[threadIdx.x] = make_float4(qx, qy, qz, norm2f(qx, qy, qz));
        }
        __syncthreads();
#pragma unroll 4
        for (int t = 0; t < TILE; ++t) {
            float d2p = dist2t(ax, ay, az, s[t]);
#pragma unroll
            for (int k = 0; k < NTH; ++k)
                c[k] += (d2p < tkp[k]) ? 1 : 0;
        }
    }
    const size_t base = ((size_t)(side * BATCH + b) * NPTS + i) * SEG + seg;
    g_cntp[base] = make_uint2((unsigned)c[0] | ((unsigned)c[1] << 16),
                              (unsigned)c[2]);
}

// ==== helper: pick k* from counts (CAP=96) ==============================
__device__ __forceinline__ int pick_ksel(const uint2 cp[SEG], int c[NTH]) {
#pragma unroll
    for (int k = 0; k < NTH; ++k) {
        c[k] = 0;
#pragma unroll
        for (int sg = 0; sg < SEG; ++sg) c[k] += cnt_at(cp[sg], k);
    }
    int ksel = 15;
#pragma unroll
    for (int k = NTH - 1; k >= 0; --k)
        if (c[k] >= KN) ksel = (c[k] <= CAP) ? k : 15;
    return ksel;
}

// ==== K2: collect candidates (transformed compare, same as count) ======
__global__ void __launch_bounds__(TPB) collect_kernel(
    const float* __restrict__ pred, const float* __restrict__ gt) {
    const int side = blockIdx.z / SEG;
    const int seg  = blockIdx.z % SEG;
    const int b = blockIdx.y;
    const int i = blockIdx.x * TPB + threadIdx.x;
    const int pidx = (side * BATCH + b) * NPTS + i;
    const float* P = (side ? gt : pred) + (size_t)b * NPTS * 3;

    const float px = P[i * 3 + 0], py = P[i * 3 + 1], pz = P[i * 3 + 2];
    const float pn = norm2f(px, py, pz);
    const float ax = -2.0f * px, ay = -2.0f * py, az = -2.0f * pz;

    uint2 cp[SEG];
#pragma unroll
    for (int sg = 0; sg < SEG; ++sg) cp[sg] = g_cntp[(size_t)pidx * SEG + sg];
    int c[NTH];
    const int ksel = pick_ksel(cp, c);
    // transformed threshold: identical pinned expression as count_kernel
    const float Tp = (ksel < NTH) ? __fadd_rn(thval(ksel), -pn)
                                  : -__int_as_float(0x7f800000);
    int slot = 0;
    for (int sg = 0; sg < seg; ++sg) slot += (ksel < NTH) ? cnt_at(cp[sg], ksel) : 0;

    __shared__ float4 s[TILE];
    const int j0 = seg * SEGLEN;

    for (int tile = 0; tile < SEGLEN; tile += TILE) {
        __syncthreads();
        {
            int j = j0 + tile + threadIdx.x;
            float qx = P[j * 3 + 0], qy = P[j * 3 + 1], qz = P[j * 3 + 2];
            s[threadIdx.x] = make_float4(qx, qy, qz, norm2f(qx, qy, qz));
        }
        __syncthreads();
#pragma unroll 4
        for (int t = 0; t < TILE; ++t) {
            float d2p = dist2t(ax, ay, az, s[t]);
            bool take = (d2p < Tp) && (slot < CAP);
            if (take) {
                g_cd2buf[(size_t)slot * NPTS2 + pidx] = __fadd_rn(d2p, pn);
                g_cidx[(size_t)slot * NPTS2 + pidx] = (unsigned short)(j0 + tile + t);
                ++slot;
            }
        }
    }
}

// === K3: heterogeneous mega: chamfer blocks + (extract+normals) blocks ==
__device__ __forceinline__ void insert16(float (&key)[KN], int (&kid)[KN],
                                          float cd, int ci) {
    bool carry = true;
#pragma unroll
    for (int k = KN - 1; k > 0; --k) {
        bool mv = carry && (cd < key[k - 1]);
        float nk = mv ? key[k - 1] : cd;
        int   ni = mv ? kid[k - 1] : ci;
        if (carry) { key[k] = nk; kid[k] = ni; }
        carry = mv;
    }
    if (carry) { key[0] = cd; kid[0] = ci; }
}

// dynamic smem: float4 tile[TILE] | float d2buf[CAP][TPB] | u16 idxbuf[CAP][TPB]
#define MEGA_SMEM (TILE * 16 + CAP * TPB * 4 + CAP * TPB * 2)

__global__ void __launch_bounds__(TPB) mega_kernel(
    const float* __restrict__ pred, const float* __restrict__ gt) {
    extern __shared__ char sm[];
    float4* s = (float4*)sm;
    const int b = blockIdx.y;
    const int tid = threadIdx.x;

    if (blockIdx.z >= 2) {
        // ------------- chamfer role (transformed min) --------------------
        const int zz = blockIdx.z - 2;
        const int side = zz / SEG;
        const int seg  = zz % SEG;
        const int i = blockIdx.x * TPB + tid;
        const float* P = (side ? gt : pred) + (size_t)b * NPTS * 3;
        const float* Q = (side ? pred : gt) + (size_t)b * NPTS * 3;

        const float px = P[i * 3 + 0], py = P[i * 3 + 1], pz = P[i * 3 + 2];
        const float pn = norm2f(px, py, pz);
        const float ax = -2.0f * px, ay = -2.0f * py, az = -2.0f * pz;
        const int j0 = seg * SEGLEN;

        float cm[4];
#pragma unroll
        for (int u = 0; u < 4; ++u) cm[u] = __int_as_float(0x7f800000);
        for (int tile = 0; tile < SEGLEN; tile += TILE) {
            __syncthreads();
            {
                int j = j0 + tile + tid;
                float qx = Q[j * 3 + 0], qy = Q[j * 3 + 1], qz = Q[j * 3 + 2];
                s[tid] = make_float4(qx, qy, qz, norm2f(qx, qy, qz));
            }
            __syncthreads();
#pragma unroll 4
            for (int t0 = 0; t0 < TILE; t0 += 4) {
#pragma unroll
                for (int u = 0; u < 4; ++u)
                    cm[u] = fminf(cm[u], dist2t(ax, ay, az, s[t0 + u]));
            }
        }
        float cmin = fminf(fminf(cm[0], cm[1]), fminf(cm[2], cm[3])) + pn;
        g_cdp[((size_t)(side * BATCH + b) * NPTS + i) * SEG + seg] = cmin;
        return;
    }

    // ------------- extract + normals role (verbatim R11 body) -----------
    float* d2buf = (float*)(sm + TILE * 16);
    unsigned short* idxbuf = (unsigned short*)(sm + TILE * 16 + CAP * TPB * 4);

    const int side = blockIdx.z;
    const int i = blockIdx.x * TPB + tid;
    const int pidx = (side * BATCH + b) * NPTS + i;
    const float* P = (side ? gt : pred) + (size_t)b * NPTS * 3;

    uint2 cp[SEG];
#pragma unroll
    for (int sg = 0; sg < SEG; ++sg) cp[sg] = g_cntp[(size_t)pidx * SEG + sg];
    int c[NTH];
    const int ksel = pick_ksel(cp, c);
    const int cnt = (ksel < NTH) ? c[ksel] : -1;

    float key[KN]; int kid[KN];

    const int anyfb = __syncthreads_or((cnt < KN) ? 1 : 0);

    if (anyfb) {
        // block-uniform exact fallback: full insert scan
        const float px = P[i * 3 + 0], py = P[i * 3 + 1], pz = P[i * 3 + 2];
        const float pn = norm2f(px, py, pz);
#pragma unroll
        for (int k = 0; k < KN; ++k) { key[k] = __int_as_float(0x7f800000); kid[k] = 0; }
        for (int tile = 0; tile < NPTS; tile += TILE) {
            __syncthreads();
            {
                int j = tile + tid;
                float qx = P[j * 3 + 0], qy = P[j * 3 + 1], qz = P[j * 3 + 2];
                s[tid] = make_float4(qx, qy, qz, norm2f(qx, qy, qz));
            }
            __syncthreads();
            for (int t = 0; t < TILE; ++t) {
                float d2 = dist2f(px, py, pz, pn, s[t]);
                if (d2 < key[KN - 1]) insert16(key, kid, d2, tile + t);
            }
        }
    } else {
        // stream candidates global->smem (coalesced across the warp)
        for (int slot = 0; slot < cnt; ++slot) {
            d2buf[slot * TPB + tid]  = g_cd2buf[(size_t)slot * NPTS2 + pidx];
            idxbuf[slot * TPB + tid] = g_cidx[(size_t)slot * NPTS2 + pidx];
        }
        // stable strict-min extraction: slots are in ascending-j order, so
        // strict '<' picks lowest index on ties == jax.lax.top_k ordering.
#pragma unroll
        for (int r = 0; r < KN; ++r) {
            float best = __int_as_float(0x7f800000);
            int bslot = 0;
            for (int j = 0; j < cnt; ++j) {
                float v = d2buf[j * TPB + tid];
                if (v < best) { best = v; bslot = j; }
            }
            key[r] = best;
            kid[r] = (int)idxbuf[bslot * TPB + tid];
            d2buf[bslot * TPB + tid] = __int_as_float(0x7f800000);
        }
    }

    // ---- repulsion from entries 1..4 (entry 0 = self) ----
    float rep = 0.0f;
#pragma unroll
    for (int k = 1; k <= 4; ++k) {
        float dd = sqrtf(fmaxf(key[k], 1e-12f));
        rep += fmaxf(0.02f - dd, 0.0f);
    }
    if (side == 0) g_rep[b * NPTS + i] = rep;

    // ---- fused normals epilogue (verbatim R11) ----
    float nbx[KN], nby[KN], nbz[KN];
#pragma unroll
    for (int k = 0; k < KN; ++k) {
        int j = kid[k];
        nbx[k] = P[j * 3 + 0]; nby[k] = P[j * 3 + 1]; nbz[k] = P[j * 3 + 2];
    }
    float mx = 0.0f, my = 0.0f, mz = 0.0f;
#pragma unroll
    for (int k = 0; k < KN; ++k) { mx += nbx[k]; my += nby[k]; mz += nbz[k]; }
    mx *= (1.0f / KN); my *= (1.0f / KN); mz *= (1.0f / KN);
    float cxx = 0, cxy = 0, cxz = 0, cyy = 0, cyz = 0, czz = 0;
#pragma unroll
    for (int k = 0; k < KN; ++k) {
        float dx = nbx[k] - mx, dy = nby[k] - my, dz = nbz[k] - mz;
        cxx += dx * dx; cxy += dx * dy; cxz += dx * dz;
        cyy += dy * dy; cyz += dy * dz; czz += dz * dz;
    }
    const float invK = 1.0f / KN;
    float cov[6] = {cxx * invK, cxy * invK, cxz * invK,
                    cyy * invK, cyz * invK, czz * invK};
    float nrm[3];
    eigvec_smallest3(cov, nrm);

    float* dst = (side == 0 ? g_nrm0 : g_nrm1) + (size_t)(b * NPTS + i) * 3;
    dst[0] = nrm[0]; dst[1] = nrm[1]; dst[2] = nrm[2];
}

// ---- deterministic two-stage reduction ----
__global__ void __launch_bounds__(RED_TPB) reduce_stage1_kernel() {
    __shared__ double sh0[RED_TPB], sh1[RED_TPB], sh2[RED_TPB], sh3[RED_TPB];
    const int tid = threadIdx.x;
    const int blk = blockIdx.x;
    const int per_blk = BN / RED_BLKS;
    const int base = blk * per_blk;
    double c0 = 0.0, c1 = 0.0, rp = 0.0, dt = 0.0;
    for (int off = tid; off < per_blk; off += RED_TPB) {
        int idx = base + off;
        const float* p0 = g_cdp + (size_t)idx * SEG;
        float a0 = fminf(fminf(p0[0], p0[1]), fminf(p0[2], p0[3]));
        const float* p1 = g_cdp + (size_t)(idx + BN) * SEG;
        float a1 = fminf(fminf(p1[0], p1[1]), fminf(p1[2], p1[3]));
        c0 += (double)a0;
        c1 += (double)a1;
        rp += (double)g_rep[idx];
        float dd = g_nrm0[idx * 3 + 0] * g_nrm1[idx * 3 + 0]
                 + g_nrm0[idx * 3 + 1] * g_nrm1[idx * 3 + 1]
                 + g_nrm0[idx * 3 + 2] * g_nrm1[idx * 3 + 2];
        dt += (double)dd;
    }
    sh0[tid] = c0; sh1[tid] = c1; sh2[tid] = rp; sh3[tid] = dt;
    __syncthreads();
    for (int off = RED_TPB / 2; off > 0; off >>= 1) {
        if (tid < off) {
            sh0[tid] += sh0[tid + off];
            sh1[tid] += sh1[tid + off];
            sh2[tid] += sh2[tid + off];
            sh3[tid] += sh3[tid + off];
        }
        __syncthreads();
    }
    if (tid == 0) {
        g_part[blk][0] = sh0[0];
        g_part[blk][1] = sh1[0];
        g_part[blk][2] = sh2[0];
        g_part[blk][3] = sh3[0];
    }
}

__global__ void __launch_bounds__(RED_BLKS) reduce_stage2_kernel(float* __restrict__ out) {
    __shared__ double sh0[RED_BLKS], sh1[RED_BLKS], sh2[RED_BLKS], sh3[RED_BLKS];
    const int tid = threadIdx.x;
    sh0[tid] = g_part[tid][0];
    sh1[tid] = g_part[tid][1];
    sh2[tid] = g_part[tid][2];
    sh3[tid] = g_part[tid][3];
    __syncthreads();
    for (int off = RED_BLKS / 2; off > 0; off >>= 1) {
        if (tid < off) {
            sh0[tid] += sh0[tid + off];
            sh1[tid] += sh1[tid + off];
            sh2[tid] += sh2[tid + off];
            sh3[tid] += sh3[tid + off];
        }
        __syncthreads();
    }
    if (tid == 0) {
        const double inv = 1.0 / (double)BN;
        double cd    = (sh0[0] + sh1[0]) * inv;
        double rep   = sh2[0] / ((double)BN * 4.0);
        double normc = 1.0 - sh3[0] * inv;
        out[0] = (float)(cd + 0.1 * rep + 0.01 * normc);
    }
}

extern "C" void kernel_launch(void* const* d_in, const int* in_sizes, int n_in,
                              void* d_out, int out_size) {
    const float* pred = (const float*)d_in[0];
    const float* gt   = (const float*)d_in[1];
    cudaFuncSetAttribute(mega_kernel,
                         cudaFuncAttributeMaxDynamicSharedMemorySize, MEGA_SMEM);
    dim3 grid_seg(NPTS / TPB, BATCH, 2 * SEG);
    dim3 grid_mega(NPTS / TPB, BATCH, 2 + 2 * SEG);  // z 0-1: extract, z 2-9: chamfer
    count_kernel<<<grid_seg, TPB>>>(pred, gt);
    collect_kernel<<<grid_seg, TPB>>>(pred, gt);
    mega_kernel<<<grid_mega, TPB, MEGA_SMEM>>>(pred, gt);
    reduce_stage1_kernel<<<RED_BLKS, RED_TPB>>>();
    reduce_stage2_kernel<<<1, RED_BLKS>>>((float*)d_out);
}